// round 11
// baseline (speedup 1.0000x reference)
#include <cuda_runtime.h>
#include <cstdint>

// Problem constants (fixed by the dataset)
#define BB   8192
#define DIN  1024
#define NC   256       // padded gating columns (120 z + 128 a + 8 pad)
#define NE   16

// ---------------- scratch (no allocation allowed) ----------------
__device__ float g_Wt  [DIN * NC];   // packed+padded gating weights [d][c]
__device__ float g_mid [BB * NC];    // gating GEMM result [b][c] (pre-bias)
__device__ float g_w   [BB * NE];    // final expert weights [b][n]

typedef unsigned long long ull;

__device__ __forceinline__ ull ffma2(ull a, ull b, ull c) {
    ull d;
    asm("fma.rn.f32x2 %0, %1, %2, %3;" : "=l"(d) : "l"(a), "l"(b), "l"(c));
    return d;
}

#define CPA16(dst, src) \
    asm volatile("cp.async.ca.shared.global [%0], [%1], 16;\n" :: "r"(dst), "l"(src))

// ---------------- kernel 0: pack Wz (15,1024,8) and Ww (16,1024,8) into [1024][256] ----------------
__global__ void prepack_kernel(const float* __restrict__ Wz, const float* __restrict__ Ww) {
    int d = blockIdx.x;
    int c = threadIdx.x;
    float v = 0.0f;
    if (c < 120) {
        v = Wz[(c >> 3) * (DIN * 8) + d * 8 + (c & 7)];
    } else if (c < 248) {
        int cc = c - 120;
        v = Ww[(cc >> 3) * (DIN * 8) + d * 8 + (cc & 7)];
    }
    g_Wt[d * NC + c] = v;
}

// ---------------- kernel 1: gating GEMM (retiled) ----------------
// CTA tile: 64 rows x 256 cols, K = 1024. 256 threads, 8 warps as 2 (row) x 4 (col):
// warp tile 32r x 64c; thread tile 8r x 8c, accumulated as 8x4 packed f32x2.
// A in smem as duplicated (a,a) float2, 8-row groups padded to 80 B (skew -> the 4
// addresses of each A LDS.128 quartet land in distinct bank groups).
// B in smem plain [kk][256 cols], cp.async double-buffered. Each warp reads only
// its own 64-col B slice (4x less crossbar traffic than round-5 layout).
#define SA_STAGE 10240   // 16 kk * 640 B  (8 groups * 80 B)
#define SB_STAGE 16384   // 16 kk * 1024 B
#define SMEM_TOT (2 * SA_STAGE + 2 * SB_STAGE)   // 53248

__global__ __launch_bounds__(256) void gemm_v3(const float* __restrict__ x) {
    extern __shared__ char sm[];
    char* sBbase = sm + 2 * SA_STAGE;
    const uint32_t sB_u = (uint32_t)__cvta_generic_to_shared(sBbase);

    const int tid    = threadIdx.x;
    const int wid    = tid >> 5;
    const int lane   = tid & 31;
    const int warp_r = wid >> 2;      // 0..1
    const int warp_c = wid & 3;       // 0..3
    const int lr     = lane >> 3;     // 0..3
    const int lc     = lane & 7;      // 0..7
    const int R0     = blockIdx.x * 64;

    // A fill mapping: thread -> (row, 4 k-values)
    const int arow = tid >> 2;        // 0..63
    const int aq   = tid & 3;         // 0..3
    const float* gA = x + (size_t)(R0 + arow) * DIN + aq * 4;
    const uint32_t aoff = (uint32_t)((arow >> 3) * 80 + (arow & 7) * 8);

    // B fill mapping: thread -> 64 bytes (16 floats) of one kk row
    const int bkk = tid >> 4;         // 0..15
    const int bcf = (tid & 15) * 16;  // col (floats)
    const char* gB = (const char*)(g_Wt + (size_t)bkk * NC + bcf);
    const uint32_t sBst = sB_u + (uint32_t)(bkk * 1024 + bcf * 4);

    // compute-side base offsets
    const uint32_t ga = (uint32_t)((warp_r * 4 + lr) * 80);
    const uint32_t gb = (uint32_t)((warp_c * 64 + lc * 8) * 4);

    ull acc[8][4];
#pragma unroll
    for (int i = 0; i < 8; i++)
#pragma unroll
        for (int p = 0; p < 4; p++) acc[i][p] = 0ull;

    // ---- prologue: stage 0 ----
    float4 av = *(const float4*)gA;
    {
        CPA16(sBst +  0, gB +  0);
        CPA16(sBst + 16, gB + 16);
        CPA16(sBst + 32, gB + 32);
        CPA16(sBst + 48, gB + 48);
        asm volatile("cp.async.commit_group;\n");
    }
#pragma unroll
    for (int j = 0; j < 4; j++) {
        float v = (&av.x)[j];
        *(float2*)(sm + (aq * 4 + j) * 640 + aoff) = make_float2(v, v);
    }
    asm volatile("cp.async.wait_group 0;\n");
    __syncthreads();

    for (int ct = 0; ct < 64; ++ct) {
        const int s = ct & 1;
        float4 anext;
        if (ct < 63) {
            anext = *(const float4*)(gA + (ct + 1) * 16);
            const char* g = gB + (size_t)(ct + 1) * 16384;   // 16 kk rows * 1024 B
            uint32_t d = sBst + (s ^ 1) * SB_STAGE;
            CPA16(d +  0, g +  0);
            CPA16(d + 16, g + 16);
            CPA16(d + 32, g + 32);
            CPA16(d + 48, g + 48);
            asm volatile("cp.async.commit_group;\n");
        }

        const char* As = sm + s * SA_STAGE;
        const char* Bs = sBbase + s * SB_STAGE;
#pragma unroll
        for (int kk = 0; kk < 16; ++kk) {
            const char* pa = As + kk * 640 + ga;
            const char* pb = Bs + kk * 1024 + gb;
            ulonglong2 qa0 = *(const ulonglong2*)(pa +  0);
            ulonglong2 qa1 = *(const ulonglong2*)(pa + 16);
            ulonglong2 qa2 = *(const ulonglong2*)(pa + 32);
            ulonglong2 qa3 = *(const ulonglong2*)(pa + 48);
            ulonglong2 qb0 = *(const ulonglong2*)(pb +  0);
            ulonglong2 qb1 = *(const ulonglong2*)(pb + 16);
            ull a[8] = {qa0.x, qa0.y, qa1.x, qa1.y, qa2.x, qa2.y, qa3.x, qa3.y};
#pragma unroll
            for (int i = 0; i < 8; i++) {
                acc[i][0] = ffma2(a[i], qb0.x, acc[i][0]);
                acc[i][1] = ffma2(a[i], qb0.y, acc[i][1]);
                acc[i][2] = ffma2(a[i], qb1.x, acc[i][2]);
                acc[i][3] = ffma2(a[i], qb1.y, acc[i][3]);
            }
        }

        if (ct < 63) {
            char* As2 = sm + (s ^ 1) * SA_STAGE;
#pragma unroll
            for (int j = 0; j < 4; j++) {
                float v = (&anext.x)[j];
                *(float2*)(As2 + (aq * 4 + j) * 640 + aoff) = make_float2(v, v);
            }
            asm volatile("cp.async.wait_group 0;\n");
        }
        __syncthreads();
    }

    // write results (pre-bias)
    float* gout = g_mid + (size_t)(R0 + warp_r * 32 + lr * 8) * NC + warp_c * 64 + lc * 8;
#pragma unroll
    for (int i = 0; i < 8; i++) {
#pragma unroll
        for (int p = 0; p < 4; p++) {
            *(float2*)(gout + (size_t)i * NC + 2 * p) = *(float2*)&acc[i][p];
        }
    }
}

// ---------------- kernel 2: per-row epilogue -> expert weights w[b][16] ----------------
__device__ __forceinline__ float smoothstep_f(float v) {
    if (v <= -0.5f) return 0.0f;
    if (v >=  0.5f) return 1.0f;
    return fmaf(-2.0f * v * v, v, fmaf(1.5f, v, 0.5f));
}

__global__ __launch_bounds__(256) void epi_kernel(const float* __restrict__ bz,
                                                  const float* __restrict__ bw,
                                                  const float* __restrict__ P) {
    const int warp = threadIdx.x >> 5;
    const int lane = threadIdx.x & 31;
    const int row  = blockIdx.x * 8 + warp;

    __shared__ float ss[8][120];
    const float* Rm = g_mid + (size_t)row * NC;

    for (int c = lane; c < 120; c += 32)
        ss[warp][c] = smoothstep_f(Rm[c] + bz[c]);
    __syncwarp();

    float L[4];
    int   q[4];
    float m = -3.4028234663852886e38f;
#pragma unroll
    for (int t = 0; t < 4; t++) {
        int qq = lane + 32 * t;
        q[t] = qq;
        int n = qq >> 3, k = qq & 7;
        float p = 1.0f;
#pragma unroll
        for (int l = 0; l < 4; l++) {
            int node = (1 << l) - 1 + (n >> (4 - l));
            int bit  = (n >> (3 - l)) & 1;
            float sv = ss[warp][node * 8 + k];
            p *= bit ? (1.0f - sv) : sv;
        }
        float lp = (p <= 0.0f) ? -3.4028234663852886e38f : __logf(p + 1e-8f);
        L[t] = Rm[120 + qq] + bw[qq] + lp;
        m = fmaxf(m, L[t]);
    }
#pragma unroll
    for (int off = 16; off; off >>= 1)
        m = fmaxf(m, __shfl_xor_sync(0xffffffffu, m, off));

    float wt[16];
#pragma unroll
    for (int l = 0; l < 16; l++) wt[l] = 0.0f;

#pragma unroll
    for (int t = 0; t < 4; t++) {
        float e = __expf(L[t] - m);   // softmax 1/sum cancels in final normalization
        int n = q[t] >> 3, k = q[t] & 7;
        const float4* Pp = (const float4*)(P + ((size_t)(k * 16 + n)) * 16);
#pragma unroll
        for (int u = 0; u < 4; u++) {
            float4 pv = Pp[u];
            wt[4 * u + 0] = fmaf(e, pv.x, wt[4 * u + 0]);
            wt[4 * u + 1] = fmaf(e, pv.y, wt[4 * u + 1]);
            wt[4 * u + 2] = fmaf(e, pv.z, wt[4 * u + 2]);
            wt[4 * u + 3] = fmaf(e, pv.w, wt[4 * u + 3]);
        }
    }
#pragma unroll
    for (int off = 16; off; off >>= 1)
#pragma unroll
        for (int l = 0; l < 16; l++)
            wt[l] += __shfl_xor_sync(0xffffffffu, wt[l], off);

    float tot = 0.0f;
#pragma unroll
    for (int l = 0; l < 16; l++) tot += wt[l];

    if (lane < 16)
        g_w[(size_t)row * 16 + lane] = wt[lane] / tot;
}

// ---------------- kernel 3: y[b][d] = sum_n f[b][d][n] * w[b][n] (DRAM-bound) ----------------
__global__ __launch_bounds__(256) void y_kernel(const float* __restrict__ f,
                                                float* __restrict__ y) {
    const int b = blockIdx.x;
    __shared__ float sw[16];
    if (threadIdx.x < 16) sw[threadIdx.x] = g_w[b * 16 + threadIdx.x];
    __syncthreads();

    float w[16];
#pragma unroll
    for (int n = 0; n < 16; n++) w[n] = sw[n];

    const float4* fb = (const float4*)(f + (size_t)b * 16384);
    float* yb = y + (size_t)b * 1024;

#pragma unroll
    for (int t = 0; t < 4; t++) {
        int d = threadIdx.x + t * 256;
        float4 v0 = fb[d * 4 + 0];
        float4 v1 = fb[d * 4 + 1];
        float4 v2 = fb[d * 4 + 2];
        float4 v3 = fb[d * 4 + 3];
        float acc;
        acc = v0.x * w[0];
        acc = fmaf(v0.y, w[1],  acc);
        acc = fmaf(v0.z, w[2],  acc);
        acc = fmaf(v0.w, w[3],  acc);
        acc = fmaf(v1.x, w[4],  acc);
        acc = fmaf(v1.y, w[5],  acc);
        acc = fmaf(v1.z, w[6],  acc);
        acc = fmaf(v1.w, w[7],  acc);
        acc = fmaf(v2.x, w[8],  acc);
        acc = fmaf(v2.y, w[9],  acc);
        acc = fmaf(v2.z, w[10], acc);
        acc = fmaf(v2.w, w[11], acc);
        acc = fmaf(v3.x, w[12], acc);
        acc = fmaf(v3.y, w[13], acc);
        acc = fmaf(v3.z, w[14], acc);
        acc = fmaf(v3.w, w[15], acc);
        yb[d] = acc;
    }
}

// ---------------- launcher: single stream, sequential ----------------
extern "C" void kernel_launch(void* const* d_in, const int* in_sizes, int n_in,
                              void* d_out, int out_size) {
    const float* f  = (const float*)d_in[0];  // (B, 1024, 16)
    const float* x  = (const float*)d_in[1];  // (B, 1024)
    const float* P  = (const float*)d_in[2];  // (8, 16, 16)
    const float* Wz = (const float*)d_in[3];  // (15, 1024, 8)
    const float* bz = (const float*)d_in[4];  // (15, 8)
    const float* Ww = (const float*)d_in[5];  // (16, 1024, 8)
    const float* bw = (const float*)d_in[6];  // (16, 8)
    float* y = (float*)d_out;                 // (B, 1024)

    static bool inited = false;
    if (!inited) {
        cudaFuncSetAttribute(gemm_v3, cudaFuncAttributeMaxDynamicSharedMemorySize, SMEM_TOT);
        inited = true;
    }

    prepack_kernel<<<DIN, 256>>>(Wz, Ww);
    gemm_v3<<<BB / 64, 256, SMEM_TOT>>>(x);
    epi_kernel<<<BB / 8, 256>>>(bz, bw, P);
    y_kernel<<<BB, 256>>>(f, y);
}

// round 12
// speedup vs baseline: 1.5187x; 1.5187x over previous
#include <cuda_runtime.h>
#include <cuda_bf16.h>
#include <cstdint>

// Problem constants (fixed by the dataset)
#define BB   8192
#define DIN  1024
#define NC   256       // padded gating columns (120 z + 128 a + 8 pad)
#define NE   16

// ---------------- scratch (no allocation allowed) ----------------
__device__ uint32_t g_Bh[DIN * NC / 2];   // W hi-split, [k][n] bf16, packed 2/word
__device__ uint32_t g_Bl[DIN * NC / 2];   // W lo-split
__device__ uint32_t g_xh[BB * DIN / 2];   // x hi-split, [b][k] bf16
__device__ uint32_t g_xl[BB * DIN / 2];   // x lo-split
__device__ float    g_mid[BB * NC];       // gating result [b][c] (pre-bias)
__device__ float    g_w  [BB * NE];       // final expert weights [b][n]

#define CPA16(dst, src) \
    asm volatile("cp.async.ca.shared.global [%0], [%1], 16;\n" :: "r"(dst), "l"(src))

#define LDSM4(r, addr) \
    asm volatile("ldmatrix.sync.aligned.m8n8.x4.shared.b16 {%0,%1,%2,%3}, [%4];" \
        : "=r"((r)[0]), "=r"((r)[1]), "=r"((r)[2]), "=r"((r)[3]) : "r"(addr))

#define LDSM4T(r, addr) \
    asm volatile("ldmatrix.sync.aligned.m8n8.x4.trans.shared.b16 {%0,%1,%2,%3}, [%4];" \
        : "=r"((r)[0]), "=r"((r)[1]), "=r"((r)[2]), "=r"((r)[3]) : "r"(addr))

#define MMA_BF16(c, a, b0, b1) \
    asm volatile("mma.sync.aligned.m16n8k16.row.col.f32.bf16.bf16.f32 " \
        "{%0,%1,%2,%3}, {%4,%5,%6,%7}, {%8,%9}, {%0,%1,%2,%3};" \
        : "+f"((c)[0]), "+f"((c)[1]), "+f"((c)[2]), "+f"((c)[3]) \
        : "r"((a)[0]), "r"((a)[1]), "r"((a)[2]), "r"((a)[3]), "r"(b0), "r"(b1))

__device__ __forceinline__ uint32_t pack_bf2(float a, float b) {
    __nv_bfloat162 h = __floats2bfloat162_rn(a, b);
    return *(uint32_t*)&h;
}

// ---------------- kernel 0a: pack + hi/lo split gating weights ----------------
// g_Bh/g_Bl layout: [k (1024)][n (256)] bf16, 2 per uint32.
__global__ void prepack_w(const float* __restrict__ Wz, const float* __restrict__ Ww) {
    int k  = blockIdx.x;      // 0..1023
    int n2 = threadIdx.x;     // 0..127 -> cols 2*n2, 2*n2+1
    float v[2];
#pragma unroll
    for (int j = 0; j < 2; j++) {
        int c = 2 * n2 + j;
        float val = 0.0f;
        if (c < 120)       val = Wz[(c >> 3) * (DIN * 8) + k * 8 + (c & 7)];
        else if (c < 248)  { int cc = c - 120; val = Ww[(cc >> 3) * (DIN * 8) + k * 8 + (cc & 7)]; }
        v[j] = val;
    }
    float h0 = __bfloat162float(__float2bfloat16(v[0]));
    float h1 = __bfloat162float(__float2bfloat16(v[1]));
    g_Bh[k * 128 + n2] = pack_bf2(h0, h1);
    g_Bl[k * 128 + n2] = pack_bf2(v[0] - h0, v[1] - h1);
}

// ---------------- kernel 0b: hi/lo split x ----------------
__global__ void prepack_x(const float* __restrict__ x) {
    int b = blockIdx.x;
    int t = threadIdx.x;
    float4 v = *(const float4*)(x + (size_t)b * DIN + t * 4);
    float hx = __bfloat162float(__float2bfloat16(v.x));
    float hy = __bfloat162float(__float2bfloat16(v.y));
    float hz = __bfloat162float(__float2bfloat16(v.z));
    float hw = __bfloat162float(__float2bfloat16(v.w));
    uint2 hi = make_uint2(pack_bf2(hx, hy), pack_bf2(hz, hw));
    uint2 lo = make_uint2(pack_bf2(v.x - hx, v.y - hy), pack_bf2(v.z - hz, v.w - hw));
    *(uint2*)(g_xh + (size_t)b * 512 + t * 2) = hi;
    *(uint2*)(g_xl + (size_t)b * 512 + t * 2) = lo;
}

// ---------------- kernel 1: gating GEMM via mma.sync bf16, 3-pass hi/lo ----------------
// CTA tile 128 m x 128 n, K chunk 32, 32 chunks. 256 threads = 8 warps (4 m x 2 n);
// warp tile 32 m x 64 n = 2 m16-tiles x 8 n8-tiles, fp32 accum (64 regs).
// smem A: [stage][hilo][128 m][80 B]  (64 B = 4x16B k-units + 16 B pad -> conflict-free LDSM)
// smem B: [stage][hilo][32 k][256 B]  (16B unit u stored at u ^ (k&7) -> conflict-free LDSM)
#define BKC      32
#define NCHUNK   (DIN / BKC)
#define A_HL     10240            // 128 * 80
#define A_STAGE  20480
#define B_HL     8192             // 32 * 256
#define B_STAGE  16384
#define SMEM_B0  (2 * A_STAGE)    // 40960
#define SMEM_TOT (2 * A_STAGE + 2 * B_STAGE)   // 73728

__global__ __launch_bounds__(256, 1) void gemm_mma(int dummy) {
    extern __shared__ char smraw[];
    const uint32_t smem = (uint32_t)__cvta_generic_to_shared(smraw);

    const int tid  = threadIdx.x;
    const int wid  = tid >> 5;
    const int lane = tid & 31;
    const int wm   = wid & 3;          // 0..3 (m band of 32)
    const int wn   = wid >> 2;         // 0..1 (n band of 64)
    const int bt   = blockIdx.x >> 1;  // row band
    const int nh   = blockIdx.x & 1;   // n half of 256
    const int R0   = bt * 128;

    // ---- fill mappings ----
    // A: thread -> (m = tid>>1, khalf = tid&1): 2x16B per hilo
    const int am = tid >> 1, ah = tid & 1;
    const uint32_t adst0 = smem + am * 80 + ah * 32;
    const char* asrc_h = (const char*)g_xh + ((size_t)(R0 + am) * DIN + ah * 16) * 2;
    const char* asrc_l = (const char*)g_xl + ((size_t)(R0 + am) * DIN + ah * 16) * 2;
    // B: thread -> (k = tid>>3, ng = tid&7): units 2ng, 2ng+1 per hilo
    const int bk = tid >> 3, bng = tid & 7;
    const int bkx = bk & 7;
    const uint32_t bdst0 = smem + SMEM_B0 + bk * 256;
    const uint32_t bu0 = (uint32_t)(((2 * bng)     ^ bkx) * 16);
    const uint32_t bu1 = (uint32_t)(((2 * bng + 1) ^ bkx) * 16);
    const char* bsrc_h = (const char*)g_Bh + ((size_t)bk * NC + nh * 128 + bng * 16) * 2;
    const char* bsrc_l = (const char*)g_Bl + ((size_t)bk * NC + nh * 128 + bng * 16) * 2;

    float acc[2][8][4];
#pragma unroll
    for (int mt = 0; mt < 2; mt++)
#pragma unroll
        for (int nt = 0; nt < 8; nt++)
#pragma unroll
            for (int e = 0; e < 4; e++) acc[mt][nt][e] = 0.0f;

    // ---- fill chunk 0 -> stage 0 ----
    {
        CPA16(adst0,                 asrc_h);
        CPA16(adst0 + 16,            asrc_h + 16);
        CPA16(adst0 + A_HL,          asrc_l);
        CPA16(adst0 + A_HL + 16,     asrc_l + 16);
        CPA16(bdst0 + bu0,           bsrc_h);
        CPA16(bdst0 + bu1,           bsrc_h + 16);
        CPA16(bdst0 + B_HL + bu0,    bsrc_l);
        CPA16(bdst0 + B_HL + bu1,    bsrc_l + 16);
        asm volatile("cp.async.commit_group;\n");
    }

    // lane decompositions for ldmatrix addressing
    const int l8  = lane & 7;
    const int lb8 = (lane >> 3) & 1;
    const int lhi = (lane >> 4) & 1;

    for (int ct = 0; ct < NCHUNK; ++ct) {
        const int s = ct & 1;
        if (ct + 1 < NCHUNK) {
            const uint32_t so = (uint32_t)((s ^ 1) * A_STAGE);
            const uint32_t sb = (uint32_t)((s ^ 1) * B_STAGE);
            const char* ah2 = asrc_h + (size_t)(ct + 1) * 64;   // +32 k * 2B
            const char* al2 = asrc_l + (size_t)(ct + 1) * 64;
            const char* bh2 = bsrc_h + (size_t)(ct + 1) * 16384; // +32 rows * 512B
            const char* bl2 = bsrc_l + (size_t)(ct + 1) * 16384;
            CPA16(adst0 + so,              ah2);
            CPA16(adst0 + so + 16,         ah2 + 16);
            CPA16(adst0 + so + A_HL,       al2);
            CPA16(adst0 + so + A_HL + 16,  al2 + 16);
            CPA16(bdst0 + sb + bu0,        bh2);
            CPA16(bdst0 + sb + bu1,        bh2 + 16);
            CPA16(bdst0 + sb + B_HL + bu0, bl2);
            CPA16(bdst0 + sb + B_HL + bu1, bl2 + 16);
            asm volatile("cp.async.commit_group;\n");
            asm volatile("cp.async.wait_group 1;\n");
        } else {
            asm volatile("cp.async.wait_group 0;\n");
        }
        __syncthreads();

        const uint32_t smA = smem + s * A_STAGE;
        const uint32_t smB = smem + SMEM_B0 + s * B_STAGE;

#pragma unroll
        for (int s2 = 0; s2 < 2; ++s2) {
            uint32_t Af[2][2][4];   // [hilo][mtile][4]
#pragma unroll
            for (int mt = 0; mt < 2; ++mt) {
                const int m_loc = wm * 32 + mt * 16 + lb8 * 8 + l8;
                const uint32_t abase = (uint32_t)(m_loc * 80 + (s2 * 2 + lhi) * 16);
                LDSM4(Af[0][mt], smA + abase);
                LDSM4(Af[1][mt], smA + A_HL + abase);
            }
            const int k_loc = s2 * 16 + lb8 * 8 + l8;
            const uint32_t brow = (uint32_t)(k_loc * 256);
            const int kx = k_loc & 7;
#pragma unroll
            for (int np = 0; np < 4; ++np) {
                const int nu = wn * 8 + np * 2 + lhi;
                const uint32_t baddr = brow + (uint32_t)((nu ^ kx) * 16);
                uint32_t Bh[4], Bl[4];
                LDSM4T(Bh, smB + baddr);
                LDSM4T(Bl, smB + B_HL + baddr);
#pragma unroll
                for (int mt = 0; mt < 2; ++mt) {
#pragma unroll
                    for (int e = 0; e < 2; ++e) {
                        float* c = acc[mt][np * 2 + e];
                        MMA_BF16(c, Af[0][mt], Bh[2 * e], Bh[2 * e + 1]);  // hi*hi
                        MMA_BF16(c, Af[0][mt], Bl[2 * e], Bl[2 * e + 1]);  // hi*lo
                        MMA_BF16(c, Af[1][mt], Bh[2 * e], Bh[2 * e + 1]);  // lo*hi
                    }
                }
            }
        }
        __syncthreads();
    }

    // ---- store (pre-bias) ----
    const int r_base = R0 + wm * 32 + (lane >> 2);
    const int c_base = nh * 128 + wn * 64 + (lane & 3) * 2;
#pragma unroll
    for (int mt = 0; mt < 2; ++mt) {
#pragma unroll
        for (int nt = 0; nt < 8; ++nt) {
            const int r = r_base + mt * 16;
            const int cc = c_base + nt * 8;
            *(float2*)&g_mid[(size_t)r * NC + cc]       = make_float2(acc[mt][nt][0], acc[mt][nt][1]);
            *(float2*)&g_mid[(size_t)(r + 8) * NC + cc] = make_float2(acc[mt][nt][2], acc[mt][nt][3]);
        }
    }
}

// ---------------- kernel 2: per-row epilogue -> expert weights w[b][16] ----------------
__device__ __forceinline__ float smoothstep_f(float v) {
    if (v <= -0.5f) return 0.0f;
    if (v >=  0.5f) return 1.0f;
    return fmaf(-2.0f * v * v, v, fmaf(1.5f, v, 0.5f));
}

__global__ __launch_bounds__(256) void epi_kernel(const float* __restrict__ bz,
                                                  const float* __restrict__ bw,
                                                  const float* __restrict__ P) {
    const int warp = threadIdx.x >> 5;
    const int lane = threadIdx.x & 31;
    const int row  = blockIdx.x * 8 + warp;

    __shared__ float ss[8][120];
    const float* Rm = g_mid + (size_t)row * NC;

    for (int c = lane; c < 120; c += 32)
        ss[warp][c] = smoothstep_f(Rm[c] + bz[c]);
    __syncwarp();

    float L[4];
    int   q[4];
    float m = -3.4028234663852886e38f;
#pragma unroll
    for (int t = 0; t < 4; t++) {
        int qq = lane + 32 * t;
        q[t] = qq;
        int n = qq >> 3, k = qq & 7;
        float p = 1.0f;
#pragma unroll
        for (int l = 0; l < 4; l++) {
            int node = (1 << l) - 1 + (n >> (4 - l));
            int bit  = (n >> (3 - l)) & 1;
            float sv = ss[warp][node * 8 + k];
            p *= bit ? (1.0f - sv) : sv;
        }
        float lp = (p <= 0.0f) ? -3.4028234663852886e38f : __logf(p + 1e-8f);
        L[t] = Rm[120 + qq] + bw[qq] + lp;
        m = fmaxf(m, L[t]);
    }
#pragma unroll
    for (int off = 16; off; off >>= 1)
        m = fmaxf(m, __shfl_xor_sync(0xffffffffu, m, off));

    float wt[16];
#pragma unroll
    for (int l = 0; l < 16; l++) wt[l] = 0.0f;

#pragma unroll
    for (int t = 0; t < 4; t++) {
        float e = __expf(L[t] - m);   // softmax 1/sum cancels in final normalization
        int n = q[t] >> 3, k = q[t] & 7;
        const float4* Pp = (const float4*)(P + ((size_t)(k * 16 + n)) * 16);
#pragma unroll
        for (int u = 0; u < 4; u++) {
            float4 pv = Pp[u];
            wt[4 * u + 0] = fmaf(e, pv.x, wt[4 * u + 0]);
            wt[4 * u + 1] = fmaf(e, pv.y, wt[4 * u + 1]);
            wt[4 * u + 2] = fmaf(e, pv.z, wt[4 * u + 2]);
            wt[4 * u + 3] = fmaf(e, pv.w, wt[4 * u + 3]);
        }
    }
#pragma unroll
    for (int off = 16; off; off >>= 1)
#pragma unroll
        for (int l = 0; l < 16; l++)
            wt[l] += __shfl_xor_sync(0xffffffffu, wt[l], off);

    float tot = 0.0f;
#pragma unroll
    for (int l = 0; l < 16; l++) tot += wt[l];

    if (lane < 16)
        g_w[(size_t)row * 16 + lane] = wt[lane] / tot;
}

// ---------------- kernel 3: y[b][d] = sum_n f[b][d][n] * w[b][n] (DRAM-bound) ----------------
__global__ __launch_bounds__(256) void y_kernel(const float* __restrict__ f,
                                                float* __restrict__ y) {
    const int b = blockIdx.x;
    __shared__ float sw[16];
    if (threadIdx.x < 16) sw[threadIdx.x] = g_w[b * 16 + threadIdx.x];
    __syncthreads();

    float w[16];
#pragma unroll
    for (int n = 0; n < 16; n++) w[n] = sw[n];

    const float4* fb = (const float4*)(f + (size_t)b * 16384);
    float* yb = y + (size_t)b * 1024;

#pragma unroll
    for (int t = 0; t < 4; t++) {
        int d = threadIdx.x + t * 256;
        float4 v0 = fb[d * 4 + 0];
        float4 v1 = fb[d * 4 + 1];
        float4 v2 = fb[d * 4 + 2];
        float4 v3 = fb[d * 4 + 3];
        float acc;
        acc = v0.x * w[0];
        acc = fmaf(v0.y, w[1],  acc);
        acc = fmaf(v0.z, w[2],  acc);
        acc = fmaf(v0.w, w[3],  acc);
        acc = fmaf(v1.x, w[4],  acc);
        acc = fmaf(v1.y, w[5],  acc);
        acc = fmaf(v1.z, w[6],  acc);
        acc = fmaf(v1.w, w[7],  acc);
        acc = fmaf(v2.x, w[8],  acc);
        acc = fmaf(v2.y, w[9],  acc);
        acc = fmaf(v2.z, w[10], acc);
        acc = fmaf(v2.w, w[11], acc);
        acc = fmaf(v3.x, w[12], acc);
        acc = fmaf(v3.y, w[13], acc);
        acc = fmaf(v3.z, w[14], acc);
        acc = fmaf(v3.w, w[15], acc);
        yb[d] = acc;
    }
}

// ---------------- launcher: single stream, sequential ----------------
extern "C" void kernel_launch(void* const* d_in, const int* in_sizes, int n_in,
                              void* d_out, int out_size) {
    const float* f  = (const float*)d_in[0];  // (B, 1024, 16)
    const float* x  = (const float*)d_in[1];  // (B, 1024)
    const float* P  = (const float*)d_in[2];  // (8, 16, 16)
    const float* Wz = (const float*)d_in[3];  // (15, 1024, 8)
    const float* bz = (const float*)d_in[4];  // (15, 8)
    const float* Ww = (const float*)d_in[5];  // (16, 1024, 8)
    const float* bw = (const float*)d_in[6];  // (16, 8)
    float* y = (float*)d_out;                 // (B, 1024)

    static bool inited = false;
    if (!inited) {
        cudaFuncSetAttribute(gemm_mma, cudaFuncAttributeMaxDynamicSharedMemorySize, SMEM_TOT);
        inited = true;
    }

    prepack_w<<<DIN, 128>>>(Wz, Ww);
    prepack_x<<<BB, 256>>>(x);
    gemm_mma<<<128, 256, SMEM_TOT>>>(0);
    epi_kernel<<<BB / 8, 256>>>(bz, bw, P);
    y_kernel<<<BB, 256>>>(f, y);
}